// round 15
// baseline (speedup 1.0000x reference)
#include <cuda_runtime.h>
#include <cuda_bf16.h>
#include <cuda_fp16.h>
#include <math.h>
#include <stdint.h>

// Problem constants (match reference)
#define N_NODES  100000
#define N_EDGES  3200000
#define IN_CH    128
#define HID_CH   128
#define OUT_CH   64
#define N_GRAPHS 128

// ---------------- scratch (device globals; no allocation allowed) ----------------
__device__ float g_deg[N_NODES];
__device__ int   g_cnt[N_NODES];
__device__ int   g_ptr[N_NODES + 1];
__device__ int   g_cursor[N_NODES];
__device__ int   g_bsum[128];
__device__ int   g_boff[128];
__device__ int2  g_csr[N_EDGES];                 // {src, __float_as_int(raw edge weight)}
__device__ __half g_y16[N_NODES * HID_CH];       // dinv-prescaled GEMM output (gather operand)
__device__ __half g_h16[N_NODES * HID_CH];       // post-aggregation activations (fp16)
__device__ float g_pool[N_GRAPHS * HID_CH];
__device__ int   g_is64;                         // 1 if index tensors are int64
// fp16-split transposed weights: wt[n*128+k] = W[k*128+n]
__device__ __half g_w1hi[HID_CH * IN_CH];
__device__ __half g_w1lo[HID_CH * IN_CH];
__device__ __half g_w2hi[HID_CH * HID_CH];
__device__ __half g_w2lo[HID_CH * HID_CH];

__device__ __forceinline__ uint32_t smem_u32(const void* p) {
    uint32_t a;
    asm("{ .reg .u64 t; cvta.to.shared.u64 t, %1; cvt.u32.u64 %0, t; }" : "=r"(a) : "l"(p));
    return a;
}

// ---------------- index accessor (int32 or int64) ----------------
__device__ __forceinline__ int load_idx(const void* p, long long i, int is64) {
    if (is64) return (int)((const long long*)p)[i];
    return ((const int*)p)[i];
}

// ---------------- merged init: dtype probe + weight split (fp16) + zeroing ----------------
__global__ void k_init(const int* ei_probe, const float* __restrict__ W1,
                       const float* __restrict__ W2) {
    int bid = blockIdx.x, tid = threadIdx.x;
    int i = bid * blockDim.x + tid;
    if (i == 0) {
        int nz = 0;
        for (int j = 0; j < 64; j++) nz |= ei_probe[2 * j + 1];
        g_is64 = (nz == 0) ? 1 : 0;
    }
    if (i < N_NODES) { g_deg[i] = 0.f; g_cnt[i] = 0; }
    if (i < N_GRAPHS * HID_CH) g_pool[i] = 0.f;
    if (bid < 128) {
        const float* W = (bid < 64) ? W1 : W2;
        __half* hi = (bid < 64) ? g_w1hi : g_w2hi;
        __half* lo = (bid < 64) ? g_w1lo : g_w2lo;
        int e = (bid & 63) * 256 + tid;          // e = k*128 + n
        int k = e >> 7, n = e & 127;
        float w = W[e];
        __half h = __float2half_rn(w);
        __half l = __float2half_rn(w - __half2float(h));
        hi[n * 128 + k] = h;
        lo[n * 128 + k] = l;
    }
}

// ---------------- pass 1: per-target edge counts ----------------
__global__ void k_pass1(const void* __restrict__ ei) {
    int e = blockIdx.x * blockDim.x + threadIdx.x;
    if (e >= N_EDGES) return;
    int c = load_idx(ei, (long long)N_EDGES + e, g_is64);
    atomicAdd(&g_cnt[c], 1);
}

// ---------------- exclusive scan of counts -> g_ptr ----------------
__global__ void k_scan1(int n) {
    __shared__ int sm[1024];
    int i = blockIdx.x * 1024 + threadIdx.x;
    int v = (i < n) ? g_cnt[i] : 0;
    sm[threadIdx.x] = v;
    __syncthreads();
    for (int off = 1; off < 1024; off <<= 1) {
        int t = (threadIdx.x >= off) ? sm[threadIdx.x - off] : 0;
        __syncthreads();
        sm[threadIdx.x] += t;
        __syncthreads();
    }
    if (i < n) g_ptr[i + 1] = sm[threadIdx.x];
    if (threadIdx.x == 1023) g_bsum[blockIdx.x] = sm[1023];
}

// parallel 128-wide exclusive scan of block sums (nb <= 128)
__global__ void k_scan2(int nb) {
    __shared__ int sm[128];
    int t = threadIdx.x;
    int v = (t < nb) ? g_bsum[t] : 0;
    sm[t] = v;
    __syncthreads();
    for (int off = 1; off < 128; off <<= 1) {
        int u = (t >= off) ? sm[t - off] : 0;
        __syncthreads();
        sm[t] += u;
        __syncthreads();
    }
    if (t < nb) g_boff[t] = sm[t] - v;   // exclusive
}

// final ptr + cursor init: cursor[i] = final_ptr[i+1] - cnt[i]
__global__ void k_scan3(int n) {
    int i = blockIdx.x * blockDim.x + threadIdx.x;
    if (i == 0) g_ptr[0] = 0;
    if (i < n) {
        int v = g_ptr[i + 1] + g_boff[i >> 10];
        g_ptr[i + 1] = v;
        g_cursor[i] = v - g_cnt[i];
    }
}

// ---------------- pass 2: fill CSR with (src, raw weight) + accumulate degree ----------------
__global__ void k_fill(const void* __restrict__ ei, const float* __restrict__ w) {
    int e = blockIdx.x * blockDim.x + threadIdx.x;
    if (e >= N_EDGES) return;
    int is64 = g_is64;
    int r = load_idx(ei, e, is64);
    int c = load_idx(ei, (long long)N_EDGES + e, is64);
    float we = w[e];
    int p = atomicAdd(&g_cursor[c], 1);
    g_csr[p] = make_int2(r, __float_as_int(we));
    atomicAdd(&g_deg[c], we);
}

// ---------------- mma.sync GEMM: Y[M,128] = fp16(dinv .* (A[M,128] @ W)) (fp16 split) ----------------
#define PADK 136
#define SME_TOTAL (3 * 128 * PADK * 2)

template <bool AHALF>
__global__ __launch_bounds__(256, 2) void k_gemm_tc(const void* __restrict__ Araw,
                                                    const __half* __restrict__ wt_hi,
                                                    const __half* __restrict__ wt_lo,
                                                    __half* __restrict__ Y, int M) {
    extern __shared__ char smem_raw[];
    __half* Ah = (__half*)smem_raw;
    __half* Al = Ah + 128 * PADK;
    __half* Bs = Al + 128 * PADK;
    int tid = threadIdx.x;
    int wid = tid >> 5, lane = tid & 31;
    int row0 = blockIdx.x * 128;

    // Load A [128x128]
    for (int g = tid; g < 128 * 32; g += 256) {
        int r = g >> 5, c4 = (g & 31) * 4;
        int gr = row0 + r;
        if (AHALF) {
            uint2 raw = make_uint2(0u, 0u);
            if (gr < M) raw = *(const uint2*)((const __half*)Araw + (size_t)gr * 128 + c4);
            *(uint2*)(Ah + r * PADK + c4) = raw;
        } else {
            float4 v = make_float4(0.f, 0.f, 0.f, 0.f);
            if (gr < M) v = ((const float4*)((const float*)Araw + (size_t)gr * 128))[c4 >> 2];
            __half h0 = __float2half_rn(v.x), h1 = __float2half_rn(v.y);
            __half h2 = __float2half_rn(v.z), h3 = __float2half_rn(v.w);
            __half* ah = Ah + r * PADK + c4;
            __half* al = Al + r * PADK + c4;
            ah[0] = h0; ah[1] = h1; ah[2] = h2; ah[3] = h3;
            al[0] = __float2half_rn(v.x - __half2float(h0));
            al[1] = __float2half_rn(v.y - __half2float(h1));
            al[2] = __float2half_rn(v.z - __half2float(h2));
            al[3] = __float2half_rn(v.w - __half2float(h3));
        }
    }
    // Load B = W_hi
    for (int g = tid; g < 128 * 16; g += 256) {
        int r = g >> 4, c8 = (g & 15) * 8;
        *(float4*)(Bs + r * PADK + c8) = *(const float4*)(wt_hi + r * 128 + c8);
    }
    __syncthreads();

    float acc[16][4];
    #pragma unroll
    for (int nt = 0; nt < 16; nt++)
        #pragma unroll
        for (int j = 0; j < 4; j++) acc[nt][j] = 0.f;

    int rowA = wid * 16;
    int a_r = rowA + (lane & 15);
    int a_c = (lane >> 4) * 8;
    int b_r = (lane & 7);
    int b_c = ((lane >> 3) & 1) * 8;

    uint32_t abase_h = smem_u32(Ah + a_r * PADK + a_c);
    uint32_t abase_l = smem_u32(Al + a_r * PADK + a_c);
    uint32_t bbase   = smem_u32(Bs + b_r * PADK + b_c);

    const int NP1 = AHALF ? 1 : 2;
    #pragma unroll
    for (int pass = 0; pass < NP1; pass++) {
        uint32_t abase = (pass == 0) ? abase_h : abase_l;
        #pragma unroll
        for (int kc = 0; kc < 8; kc++) {
            uint32_t a0, a1, a2, a3;
            asm volatile("ldmatrix.sync.aligned.m8n8.x4.shared.b16 {%0,%1,%2,%3}, [%4];"
                         : "=r"(a0), "=r"(a1), "=r"(a2), "=r"(a3)
                         : "r"(abase + kc * 32));
            #pragma unroll
            for (int nt = 0; nt < 16; nt++) {
                uint32_t b0, b1;
                asm volatile("ldmatrix.sync.aligned.m8n8.x2.shared.b16 {%0,%1}, [%2];"
                             : "=r"(b0), "=r"(b1)
                             : "r"(bbase + (uint32_t)(nt * 8 * PADK * 2) + kc * 32));
                asm volatile("mma.sync.aligned.m16n8k16.row.col.f32.f16.f16.f32 "
                             "{%0,%1,%2,%3}, {%4,%5,%6,%7}, {%8,%9}, {%0,%1,%2,%3};"
                             : "+f"(acc[nt][0]), "+f"(acc[nt][1]), "+f"(acc[nt][2]), "+f"(acc[nt][3])
                             : "r"(a0), "r"(a1), "r"(a2), "r"(a3), "r"(b0), "r"(b1));
            }
        }
    }

    // swap B to W_lo
    __syncthreads();
    for (int g = tid; g < 128 * 16; g += 256) {
        int r = g >> 4, c8 = (g & 15) * 8;
        *(float4*)(Bs + r * PADK + c8) = *(const float4*)(wt_lo + r * 128 + c8);
    }
    __syncthreads();

    // pass A_hi·Bl
    #pragma unroll
    for (int kc = 0; kc < 8; kc++) {
        uint32_t a0, a1, a2, a3;
        asm volatile("ldmatrix.sync.aligned.m8n8.x4.shared.b16 {%0,%1,%2,%3}, [%4];"
                     : "=r"(a0), "=r"(a1), "=r"(a2), "=r"(a3)
                     : "r"(abase_h + kc * 32));
        #pragma unroll
        for (int nt = 0; nt < 16; nt++) {
            uint32_t b0, b1;
            asm volatile("ldmatrix.sync.aligned.m8n8.x2.shared.b16 {%0,%1}, [%2];"
                         : "=r"(b0), "=r"(b1)
                         : "r"(bbase + (uint32_t)(nt * 8 * PADK * 2) + kc * 32));
            asm volatile("mma.sync.aligned.m16n8k16.row.col.f32.f16.f16.f32 "
                         "{%0,%1,%2,%3}, {%4,%5,%6,%7}, {%8,%9}, {%0,%1,%2,%3};"
                         : "+f"(acc[nt][0]), "+f"(acc[nt][1]), "+f"(acc[nt][2]), "+f"(acc[nt][3])
                         : "r"(a0), "r"(a1), "r"(a2), "r"(a3), "r"(b0), "r"(b1));
        }
    }

    // Epilogue: scale by rsqrt(deg+1), pack to fp16.
    int er0 = row0 + rowA + (lane >> 2);
    int er1 = er0 + 8;
    int ec = (lane & 3) * 2;
    float d0 = (er0 < M) ? rsqrtf(g_deg[er0] + 1.0f) : 0.f;
    float d1 = (er1 < M) ? rsqrtf(g_deg[er1] + 1.0f) : 0.f;
    #pragma unroll
    for (int nt = 0; nt < 16; nt++) {
        if (er0 < M)
            *(__half2*)(Y + (size_t)er0 * 128 + nt * 8 + ec) =
                __floats2half2_rn(acc[nt][0] * d0, acc[nt][1] * d0);
        if (er1 < M)
            *(__half2*)(Y + (size_t)er1 * 128 + nt * 8 + ec) =
                __floats2half2_rn(acc[nt][2] * d1, acc[nt][3] * d1);
    }
}

// ---------------- core aggregation for one node (warp-collective), returns float4 ----------------
__device__ __forceinline__ float4 agg_node(const __half* __restrict__ y, int node, int lane, int ch) {
    int beg = g_ptr[node], end = g_ptr[node + 1];
    float a0 = 0.f, a1 = 0.f, a2 = 0.f, a3 = 0.f;
    for (int e = beg; e < end; e += 32) {
        int n = min(32, end - e);
        int2 ed = (lane < n) ? g_csr[e + lane] : make_int2(0, 0);
        int j = 0;
        for (; j + 1 < n; j += 2) {
            int   s0 = __shfl_sync(0xffffffffu, ed.x, j);
            float w0 = __int_as_float(__shfl_sync(0xffffffffu, ed.y, j));
            int   s1 = __shfl_sync(0xffffffffu, ed.x, j + 1);
            float w1 = __int_as_float(__shfl_sync(0xffffffffu, ed.y, j + 1));
            float2 r0 = *(const float2*)(y + (size_t)s0 * 128 + ch);
            float2 r1 = *(const float2*)(y + (size_t)s1 * 128 + ch);
            float2 p0 = __half22float2(*(__half2*)&r0.x);
            float2 p1 = __half22float2(*(__half2*)&r0.y);
            float2 q0 = __half22float2(*(__half2*)&r1.x);
            float2 q1 = __half22float2(*(__half2*)&r1.y);
            a0 = fmaf(p0.x, w0, a0); a1 = fmaf(p0.y, w0, a1);
            a2 = fmaf(p1.x, w0, a2); a3 = fmaf(p1.y, w0, a3);
            a0 = fmaf(q0.x, w1, a0); a1 = fmaf(q0.y, w1, a1);
            a2 = fmaf(q1.x, w1, a2); a3 = fmaf(q1.y, w1, a3);
        }
        if (j < n) {
            int   s0 = __shfl_sync(0xffffffffu, ed.x, j);
            float w0 = __int_as_float(__shfl_sync(0xffffffffu, ed.y, j));
            float2 r0 = *(const float2*)(y + (size_t)s0 * 128 + ch);
            float2 p0 = __half22float2(*(__half2*)&r0.x);
            float2 p1 = __half22float2(*(__half2*)&r0.y);
            a0 = fmaf(p0.x, w0, a0); a1 = fmaf(p0.y, w0, a1);
            a2 = fmaf(p1.x, w0, a2); a3 = fmaf(p1.y, w0, a3);
        }
    }
    // self loop: +y_i (weight 1 in prescaled space)
    float2 r0 = *(const float2*)(y + (size_t)node * 128 + ch);
    float2 p0 = __half22float2(*(__half2*)&r0.x);
    float2 p1 = __half22float2(*(__half2*)&r0.y);
    a0 += p0.x; a1 += p0.y; a2 += p1.x; a3 += p1.y;
    return make_float4(a0, a1, a2, a3);
}

// ---------------- aggregation layer 1: write fp16 h ----------------
__global__ void k_agg(const __half* __restrict__ y, const float* __restrict__ bias,
                      __half* __restrict__ out) {
    int node = (blockIdx.x * blockDim.x + threadIdx.x) >> 5;
    if (node >= N_NODES) return;
    int lane = threadIdx.x & 31;
    int ch = lane * 4;
    float4 a = agg_node(y, node, lane, ch);
    float di = rsqrtf(g_deg[node] + 1.0f);
    float4 b = *(const float4*)(bias + ch);
    float o0 = fmaxf(fmaf(di, a.x, b.x), 0.f);
    float o1 = fmaxf(fmaf(di, a.y, b.y), 0.f);
    float o2 = fmaxf(fmaf(di, a.z, b.z), 0.f);
    float o3 = fmaxf(fmaf(di, a.w, b.w), 0.f);
    __half2 h01 = __floats2half2_rn(o0, o1);
    __half2 h23 = __floats2half2_rn(o2, o3);
    uint2 packed = make_uint2(*(uint32_t*)&h01, *(uint32_t*)&h23);
    *(uint2*)(out + (size_t)node * 128 + ch) = packed;
}

// ---------------- aggregation layer 2 fused with pooling ----------------
__global__ void k_agg_pool(const __half* __restrict__ y, const float* __restrict__ bias,
                           const void* __restrict__ batch) {
    __shared__ float pacc[128];
    __shared__ int   sg[8];
    int tid = threadIdx.x;
    int wid = tid >> 5, lane = tid & 31;
    int node = blockIdx.x * 8 + wid;
    bool valid = node < N_NODES;
    int ch = lane * 4;

    int gid = -1;
    if (valid) gid = load_idx(batch, node, g_is64);
    if (lane == 0) sg[wid] = gid;
    if (tid < 128) pacc[tid] = 0.f;

    float4 o = make_float4(0.f, 0.f, 0.f, 0.f);
    if (valid) {
        float4 a = agg_node(y, node, lane, ch);
        float di = rsqrtf(g_deg[node] + 1.0f);
        float4 b = *(const float4*)(bias + ch);
        o.x = fmaxf(fmaf(di, a.x, b.x), 0.f);
        o.y = fmaxf(fmaf(di, a.y, b.y), 0.f);
        o.z = fmaxf(fmaf(di, a.z, b.z), 0.f);
        o.w = fmaxf(fmaf(di, a.w, b.w), 0.f);
    }
    __syncthreads();

    int g0 = sg[0];
    bool uni = true;
    #pragma unroll
    for (int w = 1; w < 8; w++) uni = uni && (sg[w] == g0 || sg[w] < 0);

    if (uni) {
        if (valid) {
            atomicAdd(&pacc[ch + 0], o.x);
            atomicAdd(&pacc[ch + 1], o.y);
            atomicAdd(&pacc[ch + 2], o.z);
            atomicAdd(&pacc[ch + 3], o.w);
        }
        __syncthreads();
        if (tid < 128 && g0 >= 0) atomicAdd(&g_pool[g0 * 128 + tid], pacc[tid]);
    } else {
        if (valid) {
            atomicAdd(&g_pool[gid * 128 + ch + 0], o.x);
            atomicAdd(&g_pool[gid * 128 + ch + 1], o.y);
            atomicAdd(&g_pool[gid * 128 + ch + 2], o.z);
            atomicAdd(&g_pool[gid * 128 + ch + 3], o.w);
        }
        __syncthreads();
    }
}

// ---------------- classifier + sigmoid ----------------
__global__ void k_final(const float* __restrict__ Wc, const float* __restrict__ bc,
                        float* __restrict__ out) {
    int g = blockIdx.x;
    int c = threadIdx.x;
    float s = bc[c];
    #pragma unroll 4
    for (int k = 0; k < 128; k++)
        s = fmaf(g_pool[g * 128 + k], Wc[k * 64 + c], s);
    out[g * 64 + c] = 1.f / (1.f + expf(-s));
}

// ---------------- launch ----------------
extern "C" void kernel_launch(void* const* d_in, const int* in_sizes, int n_in,
                              void* d_out, int out_size) {
    const float* x     = (const float*)d_in[0];
    const void*  ei    = d_in[1];
    const float* ew    = (const float*)d_in[2];
    const void*  batch = d_in[3];
    const float* W1    = (const float*)d_in[4];
    const float* b1    = (const float*)d_in[5];
    const float* W2    = (const float*)d_in[6];
    const float* b2    = (const float*)d_in[7];
    const float* Wc    = (const float*)d_in[8];
    const float* bc    = (const float*)d_in[9];
    float* out = (float*)d_out;

    cudaFuncSetAttribute(k_gemm_tc<false>, cudaFuncAttributeMaxDynamicSharedMemorySize, SME_TOTAL);
    cudaFuncSetAttribute(k_gemm_tc<true>,  cudaFuncAttributeMaxDynamicSharedMemorySize, SME_TOTAL);

    __half* d_y; cudaGetSymbolAddress((void**)&d_y, g_y16);
    __half* d_h; cudaGetSymbolAddress((void**)&d_h, g_h16);
    __half *d_w1hi, *d_w1lo, *d_w2hi, *d_w2lo;
    cudaGetSymbolAddress((void**)&d_w1hi, g_w1hi);
    cudaGetSymbolAddress((void**)&d_w1lo, g_w1lo);
    cudaGetSymbolAddress((void**)&d_w2hi, g_w2hi);
    cudaGetSymbolAddress((void**)&d_w2lo, g_w2lo);

    const int TB = 256;
    const int egrid = (N_EDGES + TB - 1) / TB;
    const int ngrid = (N_NODES + TB - 1) / TB;
    const int nb_scan = (N_NODES + 1023) / 1024;
    const int wgrid = (N_NODES * 32 + TB - 1) / TB;   // warp per node
    const int mma_grid = (N_NODES + 127) / 128;

    // init + CSR build (count -> scan -> fill(+deg)); dinv computed inline by consumers
    k_init<<<ngrid, TB>>>((const int*)ei, W1, W2);
    k_pass1<<<egrid, TB>>>(ei);
    k_scan1<<<nb_scan, 1024>>>(N_NODES);
    k_scan2<<<1, 128>>>(nb_scan);
    k_scan3<<<ngrid, TB>>>(N_NODES);
    k_fill<<<egrid, TB>>>(ei, ew);

    // layer 1 (A = fp32 x, fp16 split, 3 passes)
    k_gemm_tc<false><<<mma_grid, 256, SME_TOTAL>>>(x, d_w1hi, d_w1lo, d_y, N_NODES);
    k_agg<<<wgrid, TB>>>(d_y, b1, d_h);
    // layer 2 (A = fp16 h exact, 2 passes; aggregation fused with pooling)
    k_gemm_tc<true><<<mma_grid, 256, SME_TOTAL>>>(d_h, d_w2hi, d_w2lo, d_y, N_NODES);
    k_agg_pool<<<(N_NODES + 7) / 8, 256>>>(d_y, b2, batch);

    // classifier
    k_final<<<N_GRAPHS, OUT_CH>>>(Wc, bc, out);

    (void)in_sizes; (void)n_in; (void)out_size;
}

// round 16
// speedup vs baseline: 1.4194x; 1.4194x over previous
#include <cuda_runtime.h>
#include <cuda_bf16.h>
#include <cuda_fp16.h>
#include <math.h>
#include <stdint.h>

// Problem constants (match reference)
#define N_NODES  100000
#define N_EDGES  3200000
#define IN_CH    128
#define HID_CH   128
#define OUT_CH   64
#define N_GRAPHS 128

// ---------------- scratch (device globals; no allocation allowed) ----------------
__device__ float g_deg[N_NODES];
__device__ int   g_cnt[N_NODES];
__device__ int   g_ptr[N_NODES + 1];
__device__ int   g_cursor[N_NODES];
__device__ int   g_bsum[128];
__device__ int   g_boff[128];
__device__ int2  g_csr[N_EDGES];                 // {src, __float_as_int(raw edge weight)}
__device__ __half g_y16[N_NODES * HID_CH];       // dinv-prescaled GEMM output (gather operand)
__device__ __half g_h16[N_NODES * HID_CH];       // post-aggregation activations (fp16)
__device__ float g_pool[N_GRAPHS * HID_CH];
__device__ int   g_is64;                         // 1 if index tensors are int64
// fp16-split transposed weights: wt[n*128+k] = W[k*128+n]
__device__ __half g_w1hi[HID_CH * IN_CH];
__device__ __half g_w1lo[HID_CH * IN_CH];
__device__ __half g_w2hi[HID_CH * HID_CH];
__device__ __half g_w2lo[HID_CH * HID_CH];

__device__ __forceinline__ uint32_t smem_u32(const void* p) {
    uint32_t a;
    asm("{ .reg .u64 t; cvta.to.shared.u64 t, %1; cvt.u32.u64 %0, t; }" : "=r"(a) : "l"(p));
    return a;
}

// ---------------- index accessor (int32 or int64) ----------------
__device__ __forceinline__ int load_idx(const void* p, long long i, int is64) {
    if (is64) return (int)((const long long*)p)[i];
    return ((const int*)p)[i];
}

// ---------------- merged init: dtype probe + weight split (fp16) + zeroing ----------------
__global__ void k_init(const int* ei_probe, const float* __restrict__ W1,
                       const float* __restrict__ W2) {
    int bid = blockIdx.x, tid = threadIdx.x;
    int i = bid * blockDim.x + tid;
    if (i == 0) {
        int nz = 0;
        for (int j = 0; j < 64; j++) nz |= ei_probe[2 * j + 1];
        g_is64 = (nz == 0) ? 1 : 0;
    }
    if (i < N_NODES) { g_deg[i] = 0.f; g_cnt[i] = 0; }
    if (i < N_GRAPHS * HID_CH) g_pool[i] = 0.f;
    if (bid < 128) {
        const float* W = (bid < 64) ? W1 : W2;
        __half* hi = (bid < 64) ? g_w1hi : g_w2hi;
        __half* lo = (bid < 64) ? g_w1lo : g_w2lo;
        int e = (bid & 63) * 256 + tid;          // e = k*128 + n
        int k = e >> 7, n = e & 127;
        float w = W[e];
        __half h = __float2half_rn(w);
        __half l = __float2half_rn(w - __half2float(h));
        hi[n * 128 + k] = h;
        lo[n * 128 + k] = l;
    }
}

// ---------------- pass 1: per-target edge counts ----------------
__global__ void k_pass1(const void* __restrict__ ei) {
    int e = blockIdx.x * blockDim.x + threadIdx.x;
    if (e >= N_EDGES) return;
    int c = load_idx(ei, (long long)N_EDGES + e, g_is64);
    atomicAdd(&g_cnt[c], 1);
}

// ---------------- exclusive scan of counts -> g_ptr ----------------
__global__ void k_scan1(int n) {
    __shared__ int sm[1024];
    int i = blockIdx.x * 1024 + threadIdx.x;
    int v = (i < n) ? g_cnt[i] : 0;
    sm[threadIdx.x] = v;
    __syncthreads();
    for (int off = 1; off < 1024; off <<= 1) {
        int t = (threadIdx.x >= off) ? sm[threadIdx.x - off] : 0;
        __syncthreads();
        sm[threadIdx.x] += t;
        __syncthreads();
    }
    if (i < n) g_ptr[i + 1] = sm[threadIdx.x];
    if (threadIdx.x == 1023) g_bsum[blockIdx.x] = sm[1023];
}

// parallel 128-wide exclusive scan of block sums (nb <= 128)
__global__ void k_scan2(int nb) {
    __shared__ int sm[128];
    int t = threadIdx.x;
    int v = (t < nb) ? g_bsum[t] : 0;
    sm[t] = v;
    __syncthreads();
    for (int off = 1; off < 128; off <<= 1) {
        int u = (t >= off) ? sm[t - off] : 0;
        __syncthreads();
        sm[t] += u;
        __syncthreads();
    }
    if (t < nb) g_boff[t] = sm[t] - v;   // exclusive
}

// final ptr + cursor init: cursor[i] = final_ptr[i+1] - cnt[i]
__global__ void k_scan3(int n) {
    int i = blockIdx.x * blockDim.x + threadIdx.x;
    if (i == 0) g_ptr[0] = 0;
    if (i < n) {
        int v = g_ptr[i + 1] + g_boff[i >> 10];
        g_ptr[i + 1] = v;
        g_cursor[i] = v - g_cnt[i];
    }
}

// ---------------- pass 2: fill CSR with (src, raw weight) + accumulate degree ----------------
__global__ void k_fill(const void* __restrict__ ei, const float* __restrict__ w) {
    int e = blockIdx.x * blockDim.x + threadIdx.x;
    if (e >= N_EDGES) return;
    int is64 = g_is64;
    int r = load_idx(ei, e, is64);
    int c = load_idx(ei, (long long)N_EDGES + e, is64);
    float we = w[e];
    int p = atomicAdd(&g_cursor[c], 1);
    g_csr[p] = make_int2(r, __float_as_int(we));
    atomicAdd(&g_deg[c], we);
}

// ---------------- mma.sync GEMM: Y[M,128] = fp16(dinv .* (A[M,128] @ W)) (fp16 split) ----------------
#define PADK 136
#define SME_TOTAL (3 * 128 * PADK * 2)

template <bool AHALF>
__global__ __launch_bounds__(256, 2) void k_gemm_tc(const void* __restrict__ Araw,
                                                    const __half* __restrict__ wt_hi,
                                                    const __half* __restrict__ wt_lo,
                                                    __half* __restrict__ Y, int M) {
    extern __shared__ char smem_raw[];
    __half* Ah = (__half*)smem_raw;
    __half* Al = Ah + 128 * PADK;
    __half* Bs = Al + 128 * PADK;
    int tid = threadIdx.x;
    int wid = tid >> 5, lane = tid & 31;
    int row0 = blockIdx.x * 128;

    // Load A [128x128]
    for (int g = tid; g < 128 * 32; g += 256) {
        int r = g >> 5, c4 = (g & 31) * 4;
        int gr = row0 + r;
        if (AHALF) {
            uint2 raw = make_uint2(0u, 0u);
            if (gr < M) raw = *(const uint2*)((const __half*)Araw + (size_t)gr * 128 + c4);
            *(uint2*)(Ah + r * PADK + c4) = raw;
        } else {
            float4 v = make_float4(0.f, 0.f, 0.f, 0.f);
            if (gr < M) v = ((const float4*)((const float*)Araw + (size_t)gr * 128))[c4 >> 2];
            __half h0 = __float2half_rn(v.x), h1 = __float2half_rn(v.y);
            __half h2 = __float2half_rn(v.z), h3 = __float2half_rn(v.w);
            __half* ah = Ah + r * PADK + c4;
            __half* al = Al + r * PADK + c4;
            ah[0] = h0; ah[1] = h1; ah[2] = h2; ah[3] = h3;
            al[0] = __float2half_rn(v.x - __half2float(h0));
            al[1] = __float2half_rn(v.y - __half2float(h1));
            al[2] = __float2half_rn(v.z - __half2float(h2));
            al[3] = __float2half_rn(v.w - __half2float(h3));
        }
    }
    // Load B = W_hi
    for (int g = tid; g < 128 * 16; g += 256) {
        int r = g >> 4, c8 = (g & 15) * 8;
        *(float4*)(Bs + r * PADK + c8) = *(const float4*)(wt_hi + r * 128 + c8);
    }
    __syncthreads();

    float acc[16][4];
    #pragma unroll
    for (int nt = 0; nt < 16; nt++)
        #pragma unroll
        for (int j = 0; j < 4; j++) acc[nt][j] = 0.f;

    int rowA = wid * 16;
    int a_r = rowA + (lane & 15);
    int a_c = (lane >> 4) * 8;
    int b_r = (lane & 7);
    int b_c = ((lane >> 3) & 1) * 8;

    uint32_t abase_h = smem_u32(Ah + a_r * PADK + a_c);
    uint32_t abase_l = smem_u32(Al + a_r * PADK + a_c);
    uint32_t bbase   = smem_u32(Bs + b_r * PADK + b_c);

    const int NP1 = AHALF ? 1 : 2;
    #pragma unroll
    for (int pass = 0; pass < NP1; pass++) {
        uint32_t abase = (pass == 0) ? abase_h : abase_l;
        #pragma unroll
        for (int kc = 0; kc < 8; kc++) {
            uint32_t a0, a1, a2, a3;
            asm volatile("ldmatrix.sync.aligned.m8n8.x4.shared.b16 {%0,%1,%2,%3}, [%4];"
                         : "=r"(a0), "=r"(a1), "=r"(a2), "=r"(a3)
                         : "r"(abase + kc * 32));
            #pragma unroll
            for (int nt = 0; nt < 16; nt++) {
                uint32_t b0, b1;
                asm volatile("ldmatrix.sync.aligned.m8n8.x2.shared.b16 {%0,%1}, [%2];"
                             : "=r"(b0), "=r"(b1)
                             : "r"(bbase + (uint32_t)(nt * 8 * PADK * 2) + kc * 32));
                asm volatile("mma.sync.aligned.m16n8k16.row.col.f32.f16.f16.f32 "
                             "{%0,%1,%2,%3}, {%4,%5,%6,%7}, {%8,%9}, {%0,%1,%2,%3};"
                             : "+f"(acc[nt][0]), "+f"(acc[nt][1]), "+f"(acc[nt][2]), "+f"(acc[nt][3])
                             : "r"(a0), "r"(a1), "r"(a2), "r"(a3), "r"(b0), "r"(b1));
            }
        }
    }

    // swap B to W_lo
    __syncthreads();
    for (int g = tid; g < 128 * 16; g += 256) {
        int r = g >> 4, c8 = (g & 15) * 8;
        *(float4*)(Bs + r * PADK + c8) = *(const float4*)(wt_lo + r * 128 + c8);
    }
    __syncthreads();

    // pass A_hi·Bl
    #pragma unroll
    for (int kc = 0; kc < 8; kc++) {
        uint32_t a0, a1, a2, a3;
        asm volatile("ldmatrix.sync.aligned.m8n8.x4.shared.b16 {%0,%1,%2,%3}, [%4];"
                     : "=r"(a0), "=r"(a1), "=r"(a2), "=r"(a3)
                     : "r"(abase_h + kc * 32));
        #pragma unroll
        for (int nt = 0; nt < 16; nt++) {
            uint32_t b0, b1;
            asm volatile("ldmatrix.sync.aligned.m8n8.x2.shared.b16 {%0,%1}, [%2];"
                         : "=r"(b0), "=r"(b1)
                         : "r"(bbase + (uint32_t)(nt * 8 * PADK * 2) + kc * 32));
            asm volatile("mma.sync.aligned.m16n8k16.row.col.f32.f16.f16.f32 "
                         "{%0,%1,%2,%3}, {%4,%5,%6,%7}, {%8,%9}, {%0,%1,%2,%3};"
                         : "+f"(acc[nt][0]), "+f"(acc[nt][1]), "+f"(acc[nt][2]), "+f"(acc[nt][3])
                         : "r"(a0), "r"(a1), "r"(a2), "r"(a3), "r"(b0), "r"(b1));
        }
    }

    // Epilogue: scale by rsqrt(deg+1), pack to fp16.
    int er0 = row0 + rowA + (lane >> 2);
    int er1 = er0 + 8;
    int ec = (lane & 3) * 2;
    float d0 = (er0 < M) ? rsqrtf(g_deg[er0] + 1.0f) : 0.f;
    float d1 = (er1 < M) ? rsqrtf(g_deg[er1] + 1.0f) : 0.f;
    #pragma unroll
    for (int nt = 0; nt < 16; nt++) {
        if (er0 < M)
            *(__half2*)(Y + (size_t)er0 * 128 + nt * 8 + ec) =
                __floats2half2_rn(acc[nt][0] * d0, acc[nt][1] * d0);
        if (er1 < M)
            *(__half2*)(Y + (size_t)er1 * 128 + nt * 8 + ec) =
                __floats2half2_rn(acc[nt][2] * d1, acc[nt][3] * d1);
    }
}

// ---------------- core aggregation for one node (warp-collective), returns float4 ----------------
__device__ __forceinline__ float4 agg_node(const __half* __restrict__ y, int node, int lane, int ch) {
    int beg = g_ptr[node], end = g_ptr[node + 1];
    float a0 = 0.f, a1 = 0.f, a2 = 0.f, a3 = 0.f;
    for (int e = beg; e < end; e += 32) {
        int n = min(32, end - e);
        int2 ed = (lane < n) ? g_csr[e + lane] : make_int2(0, 0);
        int j = 0;
        for (; j + 1 < n; j += 2) {
            int   s0 = __shfl_sync(0xffffffffu, ed.x, j);
            float w0 = __int_as_float(__shfl_sync(0xffffffffu, ed.y, j));
            int   s1 = __shfl_sync(0xffffffffu, ed.x, j + 1);
            float w1 = __int_as_float(__shfl_sync(0xffffffffu, ed.y, j + 1));
            float2 r0 = *(const float2*)(y + (size_t)s0 * 128 + ch);
            float2 r1 = *(const float2*)(y + (size_t)s1 * 128 + ch);
            float2 p0 = __half22float2(*(__half2*)&r0.x);
            float2 p1 = __half22float2(*(__half2*)&r0.y);
            float2 q0 = __half22float2(*(__half2*)&r1.x);
            float2 q1 = __half22float2(*(__half2*)&r1.y);
            a0 = fmaf(p0.x, w0, a0); a1 = fmaf(p0.y, w0, a1);
            a2 = fmaf(p1.x, w0, a2); a3 = fmaf(p1.y, w0, a3);
            a0 = fmaf(q0.x, w1, a0); a1 = fmaf(q0.y, w1, a1);
            a2 = fmaf(q1.x, w1, a2); a3 = fmaf(q1.y, w1, a3);
        }
        if (j < n) {
            int   s0 = __shfl_sync(0xffffffffu, ed.x, j);
            float w0 = __int_as_float(__shfl_sync(0xffffffffu, ed.y, j));
            float2 r0 = *(const float2*)(y + (size_t)s0 * 128 + ch);
            float2 p0 = __half22float2(*(__half2*)&r0.x);
            float2 p1 = __half22float2(*(__half2*)&r0.y);
            a0 = fmaf(p0.x, w0, a0); a1 = fmaf(p0.y, w0, a1);
            a2 = fmaf(p1.x, w0, a2); a3 = fmaf(p1.y, w0, a3);
        }
    }
    // self loop: +y_i (weight 1 in prescaled space)
    float2 r0 = *(const float2*)(y + (size_t)node * 128 + ch);
    float2 p0 = __half22float2(*(__half2*)&r0.x);
    float2 p1 = __half22float2(*(__half2*)&r0.y);
    a0 += p0.x; a1 += p0.y; a2 += p1.x; a3 += p1.y;
    return make_float4(a0, a1, a2, a3);
}

// ---------------- aggregation layer 1: write fp16 h ----------------
__global__ void k_agg(const __half* __restrict__ y, const float* __restrict__ bias,
                      __half* __restrict__ out) {
    int node = (blockIdx.x * blockDim.x + threadIdx.x) >> 5;
    if (node >= N_NODES) return;
    int lane = threadIdx.x & 31;
    int ch = lane * 4;
    float4 a = agg_node(y, node, lane, ch);
    float di = rsqrtf(g_deg[node] + 1.0f);
    float4 b = *(const float4*)(bias + ch);
    float o0 = fmaxf(fmaf(di, a.x, b.x), 0.f);
    float o1 = fmaxf(fmaf(di, a.y, b.y), 0.f);
    float o2 = fmaxf(fmaf(di, a.z, b.z), 0.f);
    float o3 = fmaxf(fmaf(di, a.w, b.w), 0.f);
    __half2 h01 = __floats2half2_rn(o0, o1);
    __half2 h23 = __floats2half2_rn(o2, o3);
    uint2 packed = make_uint2(*(uint32_t*)&h01, *(uint32_t*)&h23);
    *(uint2*)(out + (size_t)node * 128 + ch) = packed;
}

// ---------------- aggregation layer 2 fused with pooling ----------------
__global__ void k_agg_pool(const __half* __restrict__ y, const float* __restrict__ bias,
                           const void* __restrict__ batch) {
    __shared__ float pacc[128];
    __shared__ int   sg[8];
    int tid = threadIdx.x;
    int wid = tid >> 5, lane = tid & 31;
    int node = blockIdx.x * 8 + wid;
    bool valid = node < N_NODES;
    int ch = lane * 4;

    int gid = -1;
    if (valid) gid = load_idx(batch, node, g_is64);
    if (lane == 0) sg[wid] = gid;
    if (tid < 128) pacc[tid] = 0.f;

    float4 o = make_float4(0.f, 0.f, 0.f, 0.f);
    if (valid) {
        float4 a = agg_node(y, node, lane, ch);
        float di = rsqrtf(g_deg[node] + 1.0f);
        float4 b = *(const float4*)(bias + ch);
        o.x = fmaxf(fmaf(di, a.x, b.x), 0.f);
        o.y = fmaxf(fmaf(di, a.y, b.y), 0.f);
        o.z = fmaxf(fmaf(di, a.z, b.z), 0.f);
        o.w = fmaxf(fmaf(di, a.w, b.w), 0.f);
    }
    __syncthreads();

    int g0 = sg[0];
    bool uni = true;
    #pragma unroll
    for (int w = 1; w < 8; w++) uni = uni && (sg[w] == g0 || sg[w] < 0);

    if (uni) {
        if (valid) {
            atomicAdd(&pacc[ch + 0], o.x);
            atomicAdd(&pacc[ch + 1], o.y);
            atomicAdd(&pacc[ch + 2], o.z);
            atomicAdd(&pacc[ch + 3], o.w);
        }
        __syncthreads();
        if (tid < 128 && g0 >= 0) atomicAdd(&g_pool[g0 * 128 + tid], pacc[tid]);
    } else {
        if (valid) {
            atomicAdd(&g_pool[gid * 128 + ch + 0], o.x);
            atomicAdd(&g_pool[gid * 128 + ch + 1], o.y);
            atomicAdd(&g_pool[gid * 128 + ch + 2], o.z);
            atomicAdd(&g_pool[gid * 128 + ch + 3], o.w);
        }
        __syncthreads();
    }
}

// ---------------- classifier + sigmoid ----------------
__global__ void k_final(const float* __restrict__ Wc, const float* __restrict__ bc,
                        float* __restrict__ out) {
    int g = blockIdx.x;
    int c = threadIdx.x;
    float s = bc[c];
    #pragma unroll 4
    for (int k = 0; k < 128; k++)
        s = fmaf(g_pool[g * 128 + k], Wc[k * 64 + c], s);
    out[g * 64 + c] = 1.f / (1.f + expf(-s));
}

// ---------------- launch ----------------
extern "C" void kernel_launch(void* const* d_in, const int* in_sizes, int n_in,
                              void* d_out, int out_size) {
    const float* x     = (const float*)d_in[0];
    const void*  ei    = d_in[1];
    const float* ew    = (const float*)d_in[2];
    const void*  batch = d_in[3];
    const float* W1    = (const float*)d_in[4];
    const float* b1    = (const float*)d_in[5];
    const float* W2    = (const float*)d_in[6];
    const float* b2    = (const float*)d_in[7];
    const float* Wc    = (const float*)d_in[8];
    const float* bc    = (const float*)d_in[9];
    float* out = (float*)d_out;

    cudaFuncSetAttribute(k_gemm_tc<false>, cudaFuncAttributeMaxDynamicSharedMemorySize, SME_TOTAL);
    cudaFuncSetAttribute(k_gemm_tc<true>,  cudaFuncAttributeMaxDynamicSharedMemorySize, SME_TOTAL);

    __half* d_y; cudaGetSymbolAddress((void**)&d_y, g_y16);
    __half* d_h; cudaGetSymbolAddress((void**)&d_h, g_h16);
    __half *d_w1hi, *d_w1lo, *d_w2hi, *d_w2lo;
    cudaGetSymbolAddress((void**)&d_w1hi, g_w1hi);
    cudaGetSymbolAddress((void**)&d_w1lo, g_w1lo);
    cudaGetSymbolAddress((void**)&d_w2hi, g_w2hi);
    cudaGetSymbolAddress((void**)&d_w2lo, g_w2lo);

    const int TB = 256;
    const int egrid = (N_EDGES + TB - 1) / TB;
    const int ngrid = (N_NODES + TB - 1) / TB;
    const int nb_scan = (N_NODES + 1023) / 1024;
    const int wgrid = (N_NODES * 32 + TB - 1) / TB;   // warp per node
    const int mma_grid = (N_NODES + 127) / 128;

    // init + CSR build (count -> scan -> fill(+deg)); dinv computed inline by consumers
    k_init<<<ngrid, TB>>>((const int*)ei, W1, W2);
    k_pass1<<<egrid, TB>>>(ei);
    k_scan1<<<nb_scan, 1024>>>(N_NODES);
    k_scan2<<<1, 128>>>(nb_scan);
    k_scan3<<<ngrid, TB>>>(N_NODES);
    k_fill<<<egrid, TB>>>(ei, ew);

    // layer 1 (A = fp32 x, fp16 split, 3 passes)
    k_gemm_tc<false><<<mma_grid, 256, SME_TOTAL>>>(x, d_w1hi, d_w1lo, d_y, N_NODES);
    k_agg<<<wgrid, TB>>>(d_y, b1, d_h);
    // layer 2 (A = fp16 h exact, 2 passes; aggregation fused with pooling)
    k_gemm_tc<true><<<mma_grid, 256, SME_TOTAL>>>(d_h, d_w2hi, d_w2lo, d_y, N_NODES);
    k_agg_pool<<<(N_NODES + 7) / 8, 256>>>(d_y, b2, batch);

    // classifier
    k_final<<<N_GRAPHS, OUT_CH>>>(Wc, bc, out);

    (void)in_sizes; (void)n_in; (void)out_size;
}